// round 14
// baseline (speedup 1.0000x reference)
#include <cuda_runtime.h>
#include <cuda_bf16.h>

#define BN_EPS 1e-3f
#define CIN 16
#define C1  64
#define C2  128
#define MAXS 20000
#define MAXN 1048576

typedef unsigned long long ull;

// ---------------- device scratch (no allocations allowed) ----------------
__device__ float2 d_W1p[(C1 / 2) * CIN];   // channel-pair p, input i: (w[2p][i], w[2p+1][i])
__device__ float2 d_b1p[C1 / 2];
__device__ float2 d_W2ap[(C2 / 2) * CIN];
__device__ float2 d_b2ap[C2 / 2];
__device__ float  d_W2bf[C2 * C1];         // [k][j], BN-scaled
__device__ float  d_b2bf[C1];
__device__ float  d_segsum[MAXS * C1];
__device__ float  d_segmaxf[MAXS * C1];
__device__ int    d_poolmax[C1];
// sort machinery
__device__ int    d_hist[MAXS];
__device__ int    d_start[MAXS + 1];
__device__ int    d_offs[MAXS];
__device__ int    d_order[MAXN];

// ---------------- f32x2 helpers (sm_100 packed fp32 SIMD) ----------------
__device__ __forceinline__ ull ffma2(ull a, ull b, ull c) {
    ull d;
    asm("fma.rn.f32x2 %0, %1, %2, %3;" : "=l"(d) : "l"(a), "l"(b), "l"(c));
    return d;
}
__device__ __forceinline__ ull fadd2(ull a, ull b) {
    ull d;
    asm("add.rn.f32x2 %0, %1, %2;" : "=l"(d) : "l"(a), "l"(b));
    return d;
}
__device__ __forceinline__ ull pack2(float lo, float hi) {
    ull d;
    asm("mov.b64 %0, {%1, %2};" : "=l"(d) : "f"(lo), "f"(hi));
    return d;
}
__device__ __forceinline__ void unpack2(ull v, float& lo, float& hi) {
    asm("mov.b64 {%0, %1}, %2;" : "=f"(lo), "=f"(hi) : "l"(v));
}

// ---------------- fold BN into linear layers, pre-interleave pairs ----------------
__global__ void fold_kernel(
    const float* __restrict__ W1,  const float* __restrict__ g1,  const float* __restrict__ b1,
    const float* __restrict__ m1,  const float* __restrict__ v1,
    const float* __restrict__ W2a, const float* __restrict__ g2a, const float* __restrict__ b2a,
    const float* __restrict__ m2a, const float* __restrict__ v2a,
    const float* __restrict__ W2b, const float* __restrict__ g2b, const float* __restrict__ b2b,
    const float* __restrict__ m2b, const float* __restrict__ v2b)
{
    int t = blockIdx.x * blockDim.x + threadIdx.x;
    int stride = gridDim.x * blockDim.x;

    for (int i = t; i < (C1 / 2) * CIN; i += stride) {
        int p = i / CIN, k = i % CIN;
        int c0 = 2 * p, c1 = 2 * p + 1;
        float s0 = g1[c0] * rsqrtf(v1[c0] + BN_EPS);
        float s1 = g1[c1] * rsqrtf(v1[c1] + BN_EPS);
        d_W1p[i] = make_float2(W1[k * C1 + c0] * s0, W1[k * C1 + c1] * s1);
    }
    for (int p = t; p < C1 / 2; p += stride) {
        int c0 = 2 * p, c1 = 2 * p + 1;
        float s0 = g1[c0] * rsqrtf(v1[c0] + BN_EPS);
        float s1 = g1[c1] * rsqrtf(v1[c1] + BN_EPS);
        d_b1p[p] = make_float2(b1[c0] - m1[c0] * s0, b1[c1] - m1[c1] * s1);
    }
    for (int i = t; i < (C2 / 2) * CIN; i += stride) {
        int p = i / CIN, k = i % CIN;
        int c0 = 2 * p, c1 = 2 * p + 1;
        float s0 = g2a[c0] * rsqrtf(v2a[c0] + BN_EPS);
        float s1 = g2a[c1] * rsqrtf(v2a[c1] + BN_EPS);
        d_W2ap[i] = make_float2(W2a[k * C2 + c0] * s0, W2a[k * C2 + c1] * s1);
    }
    for (int p = t; p < C2 / 2; p += stride) {
        int c0 = 2 * p, c1 = 2 * p + 1;
        float s0 = g2a[c0] * rsqrtf(v2a[c0] + BN_EPS);
        float s1 = g2a[c1] * rsqrtf(v2a[c1] + BN_EPS);
        d_b2ap[p] = make_float2(b2a[c0] - m2a[c0] * s0, b2a[c1] - m2a[c1] * s1);
    }
    for (int i = t; i < C2 * C1; i += stride) {
        int j = i % C1;
        float s = g2b[j] * rsqrtf(v2b[j] + BN_EPS);
        d_W2bf[i] = W2b[i] * s;
    }
    for (int c = t; c < C1; c += stride) {
        float s = g2b[c] * rsqrtf(v2b[c] + BN_EPS);
        d_b2bf[c] = b2b[c] - m2b[c] * s;
        d_poolmax[c] = 0;
    }
    for (int i = t; i < MAXS; i += stride) d_hist[i] = 0;
}

// ---------------- counting sort: histogram -> scan -> scatter ----------------
__global__ void hist_kernel(const int* __restrict__ seg, int N)
{
    int i = blockIdx.x * blockDim.x + threadIdx.x;
    if (i < N) atomicAdd(&d_hist[seg[i]], 1);
}

__global__ void scan_kernel(int S, int N)   // single block, 1024 threads
{
    int tid = threadIdx.x;
    int per = (S + 1023) / 1024;
    int lo = tid * per;
    int hi = lo + per; if (hi > S) hi = S; if (lo > S) lo = S;

    int local = 0;
    for (int i = lo; i < hi; i++) local += d_hist[i];

    int lane = tid & 31, wid = tid >> 5;
    int v = local;
#pragma unroll
    for (int d = 1; d < 32; d <<= 1) {
        int t2 = __shfl_up_sync(0xffffffffu, v, d);
        if (lane >= d) v += t2;
    }
    __shared__ int wsum[32];
    if (lane == 31) wsum[wid] = v;
    __syncthreads();
    if (wid == 0) {
        int w = wsum[lane];
#pragma unroll
        for (int d = 1; d < 32; d <<= 1) {
            int t2 = __shfl_up_sync(0xffffffffu, w, d);
            if (lane >= d) w += t2;
        }
        wsum[lane] = w;
    }
    __syncthreads();
    int excl = v - local + (wid > 0 ? wsum[wid - 1] : 0);

    int run = excl;
    for (int i = lo; i < hi; i++) {
        int h = d_hist[i];
        d_start[i] = run;
        d_offs[i]  = run;
        run += h;
    }
    if (tid == 0) d_start[S] = N;
}

__global__ void scatter_kernel(const int* __restrict__ seg, int N)
{
    int i = blockIdx.x * blockDim.x + threadIdx.x;
    if (i < N) {
        int pos = atomicAdd(&d_offs[seg[i]], 1);
        d_order[pos] = i;
    }
}

// ---------------- branch 2: 16 -> 128 -> 64, global channel max ----------------
// 1 row x 32 channels per thread (even/odd pair shares a row), <=128 regs ->
// 2 CTAs/SM -> 4 warps/SMSP for latency hiding (occ was the binder at 12.5%).
__global__ __launch_bounds__(256, 2)
void branch2_kernel(const float* __restrict__ inp, int N)
{
    __shared__ __align__(16) ull   sW2ap[(C2 / 2) * CIN];    // 8 KB
    __shared__ __align__(16) float sW2b[C2 * C1];            // 32 KB
    __shared__ ull  sb2ap[C2 / 2];
    __shared__ ull  sb2b2[C1 / 2];
    __shared__ int  spool[C1];

    const int tx = threadIdx.x;
    for (int i = tx; i < (C2 / 2) * CIN; i += 256) sW2ap[i] = ((const ull*)d_W2ap)[i];
    for (int i = tx; i < C2 * C1; i += 256)        sW2b[i]  = d_W2bf[i];
    if (tx < C1 / 2)  sb2b2[tx] = ((const ull*)d_b2bf)[tx];
    if (tx < C2 / 2)  sb2ap[tx] = ((const ull*)d_b2ap)[tx];
    if (tx < C1)      spool[tx] = 0;
    __syncthreads();

    const int ch = tx & 1;            // channel half: 0 -> 0..31, 1 -> 32..63
    const int co = ch << 4;           // acc offset in ull pairs

    float pool[32];
#pragma unroll
    for (int j = 0; j < 32; j++) pool[j] = 0.0f;

    const int g = blockIdx.x * 256 + tx;
    const int rstride = (gridDim.x * 256) >> 1;   // pair of threads per row
    for (int r = g >> 1; r < N; r += rstride) {
        const float4* ip = (const float4*)(inp + (size_t)r * CIN);
        ull xp[CIN];
#pragma unroll
        for (int q = 0; q < 4; q++) {
            float4 v = ip[q];
            xp[4 * q + 0] = pack2(v.x, v.x);
            xp[4 * q + 1] = pack2(v.y, v.y);
            xp[4 * q + 2] = pack2(v.z, v.z);
            xp[4 * q + 3] = pack2(v.w, v.w);
        }

        ull acc[16];
#pragma unroll
        for (int jp = 0; jp < 16; jp++) acc[jp] = sb2b2[co + jp];

#pragma unroll 1
        for (int p = 0; p < C2 / 2; p++) {
            const ulonglong2* w = (const ulonglong2*)(sW2ap + p * CIN);
            ull a0 = sb2ap[p], a1 = 0ull;
#pragma unroll
            for (int i = 0; i < 4; i++) {
                ulonglong2 wa = w[2 * i];
                ulonglong2 wb = w[2 * i + 1];
                a0 = ffma2(xp[4 * i + 0], wa.x, a0);
                a1 = ffma2(xp[4 * i + 1], wa.y, a1);
                a0 = ffma2(xp[4 * i + 2], wb.x, a0);
                a1 = ffma2(xp[4 * i + 3], wb.y, a1);
            }
            a0 = fadd2(a0, a1);
            float h0, h1;
            unpack2(a0, h0, h1);
            h0 = fmaxf(h0, 0.0f);
            h1 = fmaxf(h1, 0.0f);
            ull hh0 = pack2(h0, h0);
            ull hh1 = pack2(h1, h1);
            // my 32-channel half of W2b rows 2p and 2p+1
            const ulonglong2* w0 = (const ulonglong2*)(sW2b + (2 * p) * C1 + (ch << 5));
            const ulonglong2* w1 = (const ulonglong2*)(sW2b + (2 * p) * C1 + C1 + (ch << 5));
#pragma unroll
            for (int jq = 0; jq < 8; jq++) {
                ulonglong2 u = w0[jq];
                ulonglong2 v = w1[jq];
                acc[2 * jq]     = ffma2(hh1, v.x, ffma2(hh0, u.x, acc[2 * jq]));
                acc[2 * jq + 1] = ffma2(hh1, v.y, ffma2(hh0, u.y, acc[2 * jq + 1]));
            }
        }
#pragma unroll
        for (int jp = 0; jp < 16; jp++) {
            float a, b;
            unpack2(acc[jp], a, b);
            pool[2 * jp]     = fmaxf(pool[2 * jp],     a);
            pool[2 * jp + 1] = fmaxf(pool[2 * jp + 1], b);
        }
    }

    // reduce across same-parity lanes (lanes alternate channel halves)
#pragma unroll
    for (int j = 0; j < 32; j++) {
        float v = pool[j];
#pragma unroll
        for (int d = 2; d < 32; d <<= 1)
            v = fmaxf(v, __shfl_xor_sync(0xffffffffu, v, d));
        if ((tx & 31) < 2)  // lane 0: ch=0 rep, lane 1: ch=1 rep
            atomicMax(&spool[((tx & 1) << 5) + j], __float_as_int(v));
    }
    __syncthreads();
    if (tx < C1) atomicMax(&d_poolmax[tx], spool[tx]);
}

// ---------------- branch 1 consumer-side: one warp per segment, no atomics ----------------
__global__ __launch_bounds__(256, 2)
void seg_kernel(const float* __restrict__ inp, int S)
{
    __shared__ ull sW1t[CIN * 32];   // transposed: [i][pair]  (conflict-free lane reads)
    __shared__ ull sb1s[32];

    const int tx = threadIdx.x;
    for (int i = tx; i < CIN * 32; i += 256) {
        int row = i >> 5, p = i & 31;
        sW1t[i] = ((const ull*)d_W1p)[p * CIN + row];
    }
    if (tx < 32) sb1s[tx] = ((const ull*)d_b1p)[tx];
    __syncthreads();

    const int gw = (blockIdx.x * 256 + tx) >> 5;   // segment id
    const int lane = tx & 31;                      // channel pair
    if (gw >= S) return;

    ull w[CIN];
#pragma unroll
    for (int i = 0; i < CIN; i++) w[i] = sW1t[(i << 5) | lane];
    const ull bias = sb1s[lane];

    const int s0 = d_start[gw], s1 = d_start[gw + 1];
    ull   sum2 = 0ull;
    float mx0 = 0.0f, mx1 = 0.0f;

    if (s0 < s1) {
        // 2-stage software pipeline: row index two ahead, row data one ahead
        int r  = d_order[s0];
        int rn = (s0 + 1 < s1) ? d_order[s0 + 1] : 0;
        const float4* ip = (const float4*)(inp + (size_t)r * CIN);
        float4 Va = ip[0], Vb = ip[1], Vc = ip[2], Vd = ip[3];

        for (int idx = s0; idx < s1; idx++) {
            int rn2 = (idx + 2 < s1) ? d_order[idx + 2] : 0;
            float4 Pa, Pb, Pc, Pd;
            if (idx + 1 < s1) {
                const float4* ipn = (const float4*)(inp + (size_t)rn * CIN);
                Pa = ipn[0]; Pb = ipn[1]; Pc = ipn[2]; Pd = ipn[3];
            }

            float xs[CIN] = {Va.x, Va.y, Va.z, Va.w, Vb.x, Vb.y, Vb.z, Vb.w,
                             Vc.x, Vc.y, Vc.z, Vc.w, Vd.x, Vd.y, Vd.z, Vd.w};
            ull a0 = bias, a1 = 0ull;
#pragma unroll
            for (int i = 0; i < CIN / 2; i++) {
                a0 = ffma2(pack2(xs[2 * i],     xs[2 * i]),     w[2 * i],     a0);
                a1 = ffma2(pack2(xs[2 * i + 1], xs[2 * i + 1]), w[2 * i + 1], a1);
            }
            a0 = fadd2(a0, a1);
            float x0, x1;
            unpack2(a0, x0, x1);
            x0 = fmaxf(x0, 0.0f);
            x1 = fmaxf(x1, 0.0f);
            sum2 = fadd2(sum2, pack2(x0, x1));
            mx0 = fmaxf(mx0, x0);
            mx1 = fmaxf(mx1, x1);

            r = rn; rn = rn2;
            Va = Pa; Vb = Pb; Vc = Pc; Vd = Pd;
        }
    }

    float sA, sB;
    unpack2(sum2, sA, sB);
    d_segsum[gw * C1 + 2 * lane]      = sA;
    d_segsum[gw * C1 + 2 * lane + 1]  = sB;
    d_segmaxf[gw * C1 + 2 * lane]     = mx0;   // >=0, empty segment -> 0 (matches clamp)
    d_segmaxf[gw * C1 + 2 * lane + 1] = mx1;
}

// ---------------- finalize: channel shuffle into output ----------------
__global__ void finalize_kernel(float* __restrict__ out, int S)
{
    int i = blockIdx.x * blockDim.x + threadIdx.x;
    if (i >= S * C1) return;
    int s = i / C1, c = i % C1;
    float sum = d_segsum[i];
    float mx  = d_segmaxf[i];
    float pl  = __int_as_float(d_poolmax[c]);
    float* o = out + (size_t)s * (3 * C1) + 3 * c;
    o[0] = sum;   // group_sum
    o[1] = mx;    // x_max
    o[2] = pl;    // max_pool broadcast
}

// ---------------- launch ----------------
extern "C" void kernel_launch(void* const* d_in, const int* in_sizes, int n_in,
                              void* d_out, int out_size)
{
    const float* inp = (const float*)d_in[0];
    const int*   seg = (const int*)d_in[1];
    const float* W1  = (const float*)d_in[3];
    const float* g1  = (const float*)d_in[4];
    const float* b1  = (const float*)d_in[5];
    const float* m1  = (const float*)d_in[6];
    const float* v1  = (const float*)d_in[7];
    const float* W2a = (const float*)d_in[8];
    const float* g2a = (const float*)d_in[9];
    const float* b2a = (const float*)d_in[10];
    const float* m2a = (const float*)d_in[11];
    const float* v2a = (const float*)d_in[12];
    const float* W2b = (const float*)d_in[13];
    const float* g2b = (const float*)d_in[14];
    const float* b2b = (const float*)d_in[15];
    const float* m2b = (const float*)d_in[16];
    const float* v2b = (const float*)d_in[17];

    int N = in_sizes[0] / CIN;
    if (N > MAXN) N = MAXN;
    int S = out_size / (3 * C1);
    if (S > MAXS) S = MAXS;

    fold_kernel<<<16, 256>>>(W1, g1, b1, m1, v1,
                             W2a, g2a, b2a, m2a, v2a,
                             W2b, g2b, b2b, m2b, v2b);

    hist_kernel<<<(N + 255) / 256, 256>>>(seg, N);
    scan_kernel<<<1, 1024>>>(S, N);

    // branch2 stays 4th so ncu's fixed capture index lands on it
    branch2_kernel<<<1184, 256>>>(inp, N);

    scatter_kernel<<<(N + 255) / 256, 256>>>(seg, N);

    seg_kernel<<<(S * 32 + 255) / 256, 256>>>(inp, S);

    int ne = S * C1;
    finalize_kernel<<<(ne + 255) / 256, 256>>>((float*)d_out, S);
}

// round 15
// speedup vs baseline: 1.7757x; 1.7757x over previous
#include <cuda_runtime.h>
#include <cuda_bf16.h>
#include <mma.h>
#include <cstdint>

#define BN_EPS 1e-3f
#define CIN 16
#define C1  64
#define C2  128
#define MAXS 20000
#define MAXN 1048576
#define GRID2 148

typedef unsigned long long ull;
using namespace nvcuda;

// ---------------- device scratch (no allocations allowed) ----------------
__device__ float2 d_W1p[(C1 / 2) * CIN];
__device__ float2 d_b1p[C1 / 2];
__device__ float2 d_W2ap[(C2 / 2) * CIN];
__device__ float2 d_b2ap[C2 / 2];
__device__ __nv_bfloat16 d_Wbhi[C2 * C1];   // W2b bf16 hi, row-major [k][j]
__device__ __nv_bfloat16 d_Wblo[C2 * C1];   // W2b bf16 residual
__device__ float  d_b2bf[C1];
__device__ float  d_partial[GRID2 * C1];    // per-block channel maxima (pre-bias)
__device__ float  d_poolf[C1];              // final relu(max + bias)
__device__ float  d_segsum[MAXS * C1];
__device__ float  d_segmaxf[MAXS * C1];
// sort machinery
__device__ int    d_hist[MAXS];
__device__ int    d_start[MAXS + 1];
__device__ int    d_offs[MAXS];
__device__ int    d_order[MAXN];

// ---------------- f32x2 helpers ----------------
__device__ __forceinline__ ull ffma2(ull a, ull b, ull c) {
    ull d;
    asm("fma.rn.f32x2 %0, %1, %2, %3;" : "=l"(d) : "l"(a), "l"(b), "l"(c));
    return d;
}
__device__ __forceinline__ ull fadd2(ull a, ull b) {
    ull d;
    asm("add.rn.f32x2 %0, %1, %2;" : "=l"(d) : "l"(a), "l"(b));
    return d;
}
__device__ __forceinline__ ull pack2(float lo, float hi) {
    ull d;
    asm("mov.b64 %0, {%1, %2};" : "=l"(d) : "f"(lo), "f"(hi));
    return d;
}
__device__ __forceinline__ void unpack2(ull v, float& lo, float& hi) {
    asm("mov.b64 {%0, %1}, %2;" : "=f"(lo), "=f"(hi) : "l"(v));
}

// ---------------- fold: BN into linears + bf16 hi/lo W2b ----------------
__global__ void fold_kernel(
    const float* __restrict__ W1,  const float* __restrict__ g1,  const float* __restrict__ b1,
    const float* __restrict__ m1,  const float* __restrict__ v1,
    const float* __restrict__ W2a, const float* __restrict__ g2a, const float* __restrict__ b2a,
    const float* __restrict__ m2a, const float* __restrict__ v2a,
    const float* __restrict__ W2b, const float* __restrict__ g2b, const float* __restrict__ b2b,
    const float* __restrict__ m2b, const float* __restrict__ v2b)
{
    int t = blockIdx.x * blockDim.x + threadIdx.x;
    int stride = gridDim.x * blockDim.x;

    for (int i = t; i < (C1 / 2) * CIN; i += stride) {
        int p = i / CIN, k = i % CIN;
        int c0 = 2 * p, c1 = 2 * p + 1;
        float s0 = g1[c0] * rsqrtf(v1[c0] + BN_EPS);
        float s1 = g1[c1] * rsqrtf(v1[c1] + BN_EPS);
        d_W1p[i] = make_float2(W1[k * C1 + c0] * s0, W1[k * C1 + c1] * s1);
    }
    for (int p = t; p < C1 / 2; p += stride) {
        int c0 = 2 * p, c1 = 2 * p + 1;
        float s0 = g1[c0] * rsqrtf(v1[c0] + BN_EPS);
        float s1 = g1[c1] * rsqrtf(v1[c1] + BN_EPS);
        d_b1p[p] = make_float2(b1[c0] - m1[c0] * s0, b1[c1] - m1[c1] * s1);
    }
    for (int i = t; i < (C2 / 2) * CIN; i += stride) {
        int p = i / CIN, k = i % CIN;
        int c0 = 2 * p, c1 = 2 * p + 1;
        float s0 = g2a[c0] * rsqrtf(v2a[c0] + BN_EPS);
        float s1 = g2a[c1] * rsqrtf(v2a[c1] + BN_EPS);
        d_W2ap[i] = make_float2(W2a[k * C2 + c0] * s0, W2a[k * C2 + c1] * s1);
    }
    for (int p = t; p < C2 / 2; p += stride) {
        int c0 = 2 * p, c1 = 2 * p + 1;
        float s0 = g2a[c0] * rsqrtf(v2a[c0] + BN_EPS);
        float s1 = g2a[c1] * rsqrtf(v2a[c1] + BN_EPS);
        d_b2ap[p] = make_float2(b2a[c0] - m2a[c0] * s0, b2a[c1] - m2a[c1] * s1);
    }
    // W2b [2C, C] row-major -> bf16 hi + residual lo
    for (int i = t; i < C2 * C1; i += stride) {
        int j = i % C1;
        float s = g2b[j] * rsqrtf(v2b[j] + BN_EPS);
        float w = W2b[i] * s;
        __nv_bfloat16 hi = __float2bfloat16(w);
        float lo = w - __bfloat162float(hi);
        d_Wbhi[i] = hi;
        d_Wblo[i] = __float2bfloat16(lo);
    }
    for (int c = t; c < C1; c += stride) {
        float s = g2b[c] * rsqrtf(v2b[c] + BN_EPS);
        d_b2bf[c] = b2b[c] - m2b[c] * s;
    }
    for (int i = t; i < MAXS; i += stride) d_hist[i] = 0;
}

// ---------------- counting sort ----------------
__global__ void hist_kernel(const int* __restrict__ seg, int N)
{
    int i = blockIdx.x * blockDim.x + threadIdx.x;
    if (i < N) atomicAdd(&d_hist[seg[i]], 1);
}

__global__ void scan_kernel(int S, int N)
{
    int tid = threadIdx.x;
    int per = (S + 1023) / 1024;
    int lo = tid * per;
    int hi = lo + per; if (hi > S) hi = S; if (lo > S) lo = S;

    int local = 0;
    for (int i = lo; i < hi; i++) local += d_hist[i];

    int lane = tid & 31, wid = tid >> 5;
    int v = local;
#pragma unroll
    for (int d = 1; d < 32; d <<= 1) {
        int t2 = __shfl_up_sync(0xffffffffu, v, d);
        if (lane >= d) v += t2;
    }
    __shared__ int wsum[32];
    if (lane == 31) wsum[wid] = v;
    __syncthreads();
    if (wid == 0) {
        int w = wsum[lane];
#pragma unroll
        for (int d = 1; d < 32; d <<= 1) {
            int t2 = __shfl_up_sync(0xffffffffu, w, d);
            if (lane >= d) w += t2;
        }
        wsum[lane] = w;
    }
    __syncthreads();
    int excl = v - local + (wid > 0 ? wsum[wid - 1] : 0);

    int run = excl;
    for (int i = lo; i < hi; i++) {
        int h = d_hist[i];
        d_start[i] = run;
        d_offs[i]  = run;
        run += h;
    }
    if (tid == 0) d_start[S] = N;
}

__global__ void scatter_kernel(const int* __restrict__ seg, int N)
{
    int i = blockIdx.x * blockDim.x + threadIdx.x;
    if (i < N) {
        int pos = atomicAdd(&d_offs[seg[i]], 1);
        d_order[pos] = i;
    }
}

// ---------------- branch 2: scalar fp32 2a + WMMA bf16x3 2b ----------------
// SMEM layout (dynamic):
#define LDH 136        // H col-major [k=128][row ld 136] bf16
#define LDB 72         // W2b row-major [k=128][j ld 72] bf16
#define LDD 132        // D col-major  [c=64][row ld 132] fp32
#define OFF_W2AP 0                       //  8192 B
#define OFF_SB2AP 8192                   //   512 B
#define OFF_HHI  8704                    // 128*136*2 = 34816
#define OFF_HLO  43520                   // 34816
#define OFF_WBHI 78336                   // 128*72*2 = 18432
#define OFF_WBLO 96768                   // 18432
#define OFF_D    115200                  // 64*132*4 = 33792
#define SMEM2_TOTAL 148992

__global__ __launch_bounds__(128, 1)
void branch2_wmma_kernel(const float* __restrict__ inp, int N, int tiles)
{
    extern __shared__ __align__(16) char sm[];
    ull*  sW2ap = (ull*)(sm + OFF_W2AP);
    ull*  sb2ap = (ull*)(sm + OFF_SB2AP);
    __nv_bfloat16* sHhi = (__nv_bfloat16*)(sm + OFF_HHI);
    __nv_bfloat16* sHlo = (__nv_bfloat16*)(sm + OFF_HLO);
    __nv_bfloat16* sWbhi = (__nv_bfloat16*)(sm + OFF_WBHI);
    __nv_bfloat16* sWblo = (__nv_bfloat16*)(sm + OFF_WBLO);
    float* sD = (float*)(sm + OFF_D);

    const int tx = threadIdx.x;
    const int w  = tx >> 5;

    for (int i = tx; i < 1024; i += 128) sW2ap[i] = ((const ull*)d_W2ap)[i];
    if (tx < 64) sb2ap[tx] = ((const ull*)d_b2ap)[tx];
    for (int i = tx; i < C2 * C1; i += 128) {
        int k = i >> 6, j = i & 63;
        sWbhi[k * LDB + j] = d_Wbhi[i];
        sWblo[k * LDB + j] = d_Wblo[i];
    }
    __syncthreads();

    float pool = -3.0e38f;          // my channel (tx>>1), my row-half ((tx&1)*64)
    const int myc = tx >> 1;
    const int myr = (tx & 1) << 6;

    for (int t = blockIdx.x; t < tiles; t += gridDim.x) {
        // ---- phase 1: fp32 2a for my row; split h -> bf16 hi/lo; col-major STS ----
        int row = t * 128 + tx;
        if (row >= N) row = N - 1;           // clamp: duplicate row, max-safe
        const float4* ip = (const float4*)(inp + (size_t)row * CIN);
        ull xp[CIN];
#pragma unroll
        for (int q = 0; q < 4; q++) {
            float4 v = ip[q];
            xp[4 * q + 0] = pack2(v.x, v.x);
            xp[4 * q + 1] = pack2(v.y, v.y);
            xp[4 * q + 2] = pack2(v.z, v.z);
            xp[4 * q + 3] = pack2(v.w, v.w);
        }
#pragma unroll 1
        for (int p = 0; p < C2 / 2; p++) {
            const ulonglong2* wv = (const ulonglong2*)(sW2ap + p * CIN);
            ull a0 = sb2ap[p], a1 = 0ull;
#pragma unroll
            for (int i = 0; i < 4; i++) {
                ulonglong2 wa = wv[2 * i];
                ulonglong2 wb = wv[2 * i + 1];
                a0 = ffma2(xp[4 * i + 0], wa.x, a0);
                a1 = ffma2(xp[4 * i + 1], wa.y, a1);
                a0 = ffma2(xp[4 * i + 2], wb.x, a0);
                a1 = ffma2(xp[4 * i + 3], wb.y, a1);
            }
            a0 = fadd2(a0, a1);
            float h0, h1;
            unpack2(a0, h0, h1);
            h0 = fmaxf(h0, 0.0f);
            h1 = fmaxf(h1, 0.0f);
            __nv_bfloat16 h0h = __float2bfloat16(h0);
            __nv_bfloat16 h1h = __float2bfloat16(h1);
            sHhi[(2 * p) * LDH + tx]     = h0h;
            sHhi[(2 * p + 1) * LDH + tx] = h1h;
            sHlo[(2 * p) * LDH + tx]     = __float2bfloat16(h0 - __bfloat162float(h0h));
            sHlo[(2 * p + 1) * LDH + tx] = __float2bfloat16(h1 - __bfloat162float(h1h));
        }
        __syncthreads();

        // ---- phase 2: WMMA D = Hhi*Whi + Hhi*Wlo + Hlo*Whi (fp32 acc) ----
        {
            wmma::fragment<wmma::accumulator, 16, 16, 16, float> acc[2][4];
#pragma unroll
            for (int mi = 0; mi < 2; mi++)
#pragma unroll
                for (int ni = 0; ni < 4; ni++)
                    wmma::fill_fragment(acc[mi][ni], 0.0f);

#pragma unroll 1
            for (int k = 0; k < 8; k++) {
                wmma::fragment<wmma::matrix_a, 16, 16, 16, __nv_bfloat16, wmma::col_major> ahi[2], alo[2];
#pragma unroll
                for (int mi = 0; mi < 2; mi++) {
                    int m = (w * 2 + mi) * 16;
                    wmma::load_matrix_sync(ahi[mi], sHhi + (k * 16) * LDH + m, LDH);
                    wmma::load_matrix_sync(alo[mi], sHlo + (k * 16) * LDH + m, LDH);
                }
#pragma unroll
                for (int ni = 0; ni < 4; ni++) {
                    wmma::fragment<wmma::matrix_b, 16, 16, 16, __nv_bfloat16, wmma::row_major> bhi, blo;
                    wmma::load_matrix_sync(bhi, sWbhi + (k * 16) * LDB + ni * 16, LDB);
                    wmma::load_matrix_sync(blo, sWblo + (k * 16) * LDB + ni * 16, LDB);
#pragma unroll
                    for (int mi = 0; mi < 2; mi++) {
                        wmma::mma_sync(acc[mi][ni], ahi[mi], bhi, acc[mi][ni]);
                        wmma::mma_sync(acc[mi][ni], ahi[mi], blo, acc[mi][ni]);
                        wmma::mma_sync(acc[mi][ni], alo[mi], bhi, acc[mi][ni]);
                    }
                }
            }
#pragma unroll
            for (int mi = 0; mi < 2; mi++)
#pragma unroll
                for (int ni = 0; ni < 4; ni++)
                    wmma::store_matrix_sync(sD + (ni * 16) * LDD + (w * 2 + mi) * 16,
                                            acc[mi][ni], LDD, wmma::mem_col_major);
        }
        __syncthreads();

        // ---- phase 3: epilogue — my channel, my 64-row half ----
        {
            const float4* dr = (const float4*)(sD + myc * LDD + myr);
#pragma unroll
            for (int q = 0; q < 16; q++) {
                float4 v = dr[q];
                pool = fmaxf(pool, fmaxf(fmaxf(v.x, v.y), fmaxf(v.z, v.w)));
            }
        }
        __syncthreads();   // sD/sH reuse protection before next tile
    }

    // combine row-halves (partner thread), write per-block partial
    float other = __shfl_xor_sync(0xffffffffu, pool, 1);
    pool = fmaxf(pool, other);
    if ((tx & 1) == 0) d_partial[blockIdx.x * C1 + myc] = pool;
}

// ---------------- reduce per-block partials -> relu(max + bias) ----------------
__global__ void pool_reduce_kernel()
{
    int c = threadIdx.x;     // 64 threads
    float m = -3.0e38f;
    for (int b = 0; b < GRID2; b++) m = fmaxf(m, d_partial[b * C1 + c]);
    d_poolf[c] = fmaxf(m + d_b2bf[c], 0.0f);
}

// ---------------- branch 1 consumer-side: one warp per segment ----------------
__global__ __launch_bounds__(256, 2)
void seg_kernel(const float* __restrict__ inp, int S)
{
    __shared__ ull sW1t[CIN * 32];
    __shared__ ull sb1s[32];

    const int tx = threadIdx.x;
    for (int i = tx; i < CIN * 32; i += 256) {
        int row = i >> 5, p = i & 31;
        sW1t[i] = ((const ull*)d_W1p)[p * CIN + row];
    }
    if (tx < 32) sb1s[tx] = ((const ull*)d_b1p)[tx];
    __syncthreads();

    const int gw = (blockIdx.x * 256 + tx) >> 5;
    const int lane = tx & 31;
    if (gw >= S) return;

    ull w[CIN];
#pragma unroll
    for (int i = 0; i < CIN; i++) w[i] = sW1t[(i << 5) | lane];
    const ull bias = sb1s[lane];

    const int s0 = d_start[gw], s1 = d_start[gw + 1];
    ull   sum2 = 0ull;
    float mx0 = 0.0f, mx1 = 0.0f;

    if (s0 < s1) {
        int r  = d_order[s0];
        int rn = (s0 + 1 < s1) ? d_order[s0 + 1] : 0;
        const float4* ip = (const float4*)(inp + (size_t)r * CIN);
        float4 Va = ip[0], Vb = ip[1], Vc = ip[2], Vd = ip[3];

        for (int idx = s0; idx < s1; idx++) {
            int rn2 = (idx + 2 < s1) ? d_order[idx + 2] : 0;
            float4 Pa, Pb, Pc, Pd;
            if (idx + 1 < s1) {
                const float4* ipn = (const float4*)(inp + (size_t)rn * CIN);
                Pa = ipn[0]; Pb = ipn[1]; Pc = ipn[2]; Pd = ipn[3];
            }

            float xs[CIN] = {Va.x, Va.y, Va.z, Va.w, Vb.x, Vb.y, Vb.z, Vb.w,
                             Vc.x, Vc.y, Vc.z, Vc.w, Vd.x, Vd.y, Vd.z, Vd.w};
            ull a0 = bias, a1 = 0ull;
#pragma unroll
            for (int i = 0; i < CIN / 2; i++) {
                a0 = ffma2(pack2(xs[2 * i],     xs[2 * i]),     w[2 * i],     a0);
                a1 = ffma2(pack2(xs[2 * i + 1], xs[2 * i + 1]), w[2 * i + 1], a1);
            }
            a0 = fadd2(a0, a1);
            float x0, x1;
            unpack2(a0, x0, x1);
            x0 = fmaxf(x0, 0.0f);
            x1 = fmaxf(x1, 0.0f);
            sum2 = fadd2(sum2, pack2(x0, x1));
            mx0 = fmaxf(mx0, x0);
            mx1 = fmaxf(mx1, x1);

            r = rn; rn = rn2;
            Va = Pa; Vb = Pb; Vc = Pc; Vd = Pd;
        }
    }

    float sA, sB;
    unpack2(sum2, sA, sB);
    d_segsum[gw * C1 + 2 * lane]      = sA;
    d_segsum[gw * C1 + 2 * lane + 1]  = sB;
    d_segmaxf[gw * C1 + 2 * lane]     = mx0;
    d_segmaxf[gw * C1 + 2 * lane + 1] = mx1;
}

// ---------------- finalize: channel shuffle into output ----------------
__global__ void finalize_kernel(float* __restrict__ out, int S)
{
    int i = blockIdx.x * blockDim.x + threadIdx.x;
    if (i >= S * C1) return;
    int s = i / C1, c = i % C1;
    float sum = d_segsum[i];
    float mx  = d_segmaxf[i];
    float pl  = d_poolf[c];
    float* o = out + (size_t)s * (3 * C1) + 3 * c;
    o[0] = sum;
    o[1] = mx;
    o[2] = pl;
}

// ---------------- launch ----------------
extern "C" void kernel_launch(void* const* d_in, const int* in_sizes, int n_in,
                              void* d_out, int out_size)
{
    const float* inp = (const float*)d_in[0];
    const int*   seg = (const int*)d_in[1];
    const float* W1  = (const float*)d_in[3];
    const float* g1  = (const float*)d_in[4];
    const float* b1  = (const float*)d_in[5];
    const float* m1  = (const float*)d_in[6];
    const float* v1  = (const float*)d_in[7];
    const float* W2a = (const float*)d_in[8];
    const float* g2a = (const float*)d_in[9];
    const float* b2a = (const float*)d_in[10];
    const float* m2a = (const float*)d_in[11];
    const float* v2a = (const float*)d_in[12];
    const float* W2b = (const float*)d_in[13];
    const float* g2b = (const float*)d_in[14];
    const float* b2b = (const float*)d_in[15];
    const float* m2b = (const float*)d_in[16];
    const float* v2b = (const float*)d_in[17];

    int N = in_sizes[0] / CIN;
    if (N > MAXN) N = MAXN;
    int S = out_size / (3 * C1);
    if (S > MAXS) S = MAXS;
    int tiles = (N + 127) / 128;

    cudaFuncSetAttribute(branch2_wmma_kernel,
                         cudaFuncAttributeMaxDynamicSharedMemorySize, SMEM2_TOTAL);

    fold_kernel<<<16, 256>>>(W1, g1, b1, m1, v1,
                             W2a, g2a, b2a, m2a, v2a,
                             W2b, g2b, b2b, m2b, v2b);

    hist_kernel<<<(N + 255) / 256, 256>>>(seg, N);
    scan_kernel<<<1, 1024>>>(S, N);

    // branch2 stays 4th so ncu's fixed capture index lands on it
    branch2_wmma_kernel<<<GRID2, 128, SMEM2_TOTAL>>>(inp, N, tiles);

    pool_reduce_kernel<<<1, 64>>>();

    scatter_kernel<<<(N + 255) / 256, 256>>>(seg, N);

    seg_kernel<<<(S * 32 + 255) / 256, 256>>>(inp, S);

    int ne = S * C1;
    finalize_kernel<<<(ne + 255) / 256, 256>>>((float*)d_out, S);
}